// round 4
// baseline (speedup 1.0000x reference)
#include <cuda_runtime.h>

#define NTHREADS 256
#define NBLOCKS  1024   // 1024*256*8 == 2097152 == n4  (8 float4 per thread)

// Module-load zero-initialized; last block resets g_count every call.
__device__ float g_partials[NBLOCKS];
__device__ unsigned int g_count = 0u;

__device__ __forceinline__ float skew_elem(float p, float t) {
    float d   = p - t;                 // y_pred - y_true
    float lam = (t - 50.0f) * 0.02f;   // both lamda branches collapse to (t-50)/50
    float arg = (d * lam < 0.0f) ? fabsf(lam) : 0.0f;   // gate <=> d*lam<0
    return fabsf(d) * __expf(arg);     // __expf(0) == 1 exactly
}

__global__ void __launch_bounds__(NTHREADS)
skew_fused_kernel(const float4* __restrict__ yp,
                  const float4* __restrict__ yt,
                  float* __restrict__ out,
                  int n4, float inv_n) {
    const int tid    = blockIdx.x * NTHREADS + threadIdx.x;
    const int stride = gridDim.x * NTHREADS;

    float s0 = 0.f, s1 = 0.f, s2 = 0.f, s3 = 0.f;

    if (n4 == stride * 8) {
        // Fast path: fixed 8 iterations, two batches of 4 front-batched pairs.
        #pragma unroll
        for (int b = 0; b < 2; b++) {
            const int i0 = tid + (b * 4 + 0) * stride;
            const int i1 = tid + (b * 4 + 1) * stride;
            const int i2 = tid + (b * 4 + 2) * stride;
            const int i3 = tid + (b * 4 + 3) * stride;
            // 8 independent LDG.128 issued back-to-back (high MLP)
            float4 p0 = yp[i0]; float4 p1 = yp[i1];
            float4 p2 = yp[i2]; float4 p3 = yp[i3];
            float4 t0 = yt[i0]; float4 t1 = yt[i1];
            float4 t2 = yt[i2]; float4 t3 = yt[i3];

            s0 += skew_elem(p0.x, t0.x); s1 += skew_elem(p0.y, t0.y);
            s2 += skew_elem(p0.z, t0.z); s3 += skew_elem(p0.w, t0.w);
            s0 += skew_elem(p1.x, t1.x); s1 += skew_elem(p1.y, t1.y);
            s2 += skew_elem(p1.z, t1.z); s3 += skew_elem(p1.w, t1.w);
            s0 += skew_elem(p2.x, t2.x); s1 += skew_elem(p2.y, t2.y);
            s2 += skew_elem(p2.z, t2.z); s3 += skew_elem(p2.w, t2.w);
            s0 += skew_elem(p3.x, t3.x); s1 += skew_elem(p3.y, t3.y);
            s2 += skew_elem(p3.z, t3.z); s3 += skew_elem(p3.w, t3.w);
        }
    } else {
        // General fallback: grid-stride.
        for (int i = tid; i < n4; i += stride) {
            float4 p = yp[i]; float4 t = yt[i];
            s0 += skew_elem(p.x, t.x); s1 += skew_elem(p.y, t.y);
            s2 += skew_elem(p.z, t.z); s3 += skew_elem(p.w, t.w);
        }
    }

    float s = (s0 + s1) + (s2 + s3);

    // warp reduce
    #pragma unroll
    for (int o = 16; o > 0; o >>= 1)
        s += __shfl_xor_sync(0xffffffffu, s, o);

    __shared__ float warp_sums[NTHREADS / 32];
    __shared__ bool is_last;
    const int lane = threadIdx.x & 31;
    const int wid  = threadIdx.x >> 5;
    if (lane == 0) warp_sums[wid] = s;
    __syncthreads();

    if (threadIdx.x == 0) {
        float v = warp_sums[0];
        #pragma unroll
        for (int w = 1; w < NTHREADS / 32; w++) v += warp_sums[w];
        g_partials[blockIdx.x] = v;          // plain STG, no atomic
        __threadfence();
        unsigned int done = atomicAdd(&g_count, 1u);
        is_last = (done == gridDim.x - 1);
    }
    __syncthreads();

    if (is_last) {
        double d = 0.0;
        for (int i = threadIdx.x; i < (int)gridDim.x; i += NTHREADS)
            d += (double)g_partials[i];
        #pragma unroll
        for (int o = 16; o > 0; o >>= 1)
            d += __shfl_xor_sync(0xffffffffu, d, o);

        __shared__ double dsum[NTHREADS / 32];
        if (lane == 0) dsum[wid] = d;
        __syncthreads();
        if (threadIdx.x == 0) {
            double total = dsum[0];
            #pragma unroll
            for (int w = 1; w < NTHREADS / 32; w++) total += dsum[w];
            out[0] = (float)(total * (double)inv_n);
            g_count = 0u;                    // reset for next graph replay
        }
    }
}

extern "C" void kernel_launch(void* const* d_in, const int* in_sizes, int n_in,
                              void* d_out, int out_size) {
    const float4* yp = (const float4*)d_in[0];  // y_pred
    const float4* yt = (const float4*)d_in[1];  // y_true
    float* out = (float*)d_out;

    int n  = in_sizes[0];       // 8388608
    int n4 = n >> 2;            // 2097152

    int blocks = NBLOCKS;
    if (blocks * NTHREADS > n4 && n4 > 0)
        blocks = (n4 + NTHREADS - 1) / NTHREADS;

    skew_fused_kernel<<<blocks, NTHREADS>>>(yp, yt, out, n4, 1.0f / (float)n);
}